// round 3
// baseline (speedup 1.0000x reference)
#include <cuda_runtime.h>

#define NN   131072
#define KK   27
#define FIN  3
#define FOUT 32
#define EPSQ 1e-5f

#define NODES  512
#define HPAD   36

// allocation-free scratch
__device__ float  g_h[NN * FOUT];       // 16 MB intermediate h
__device__ float4 g_x4[NN];             // 2 MB padded x
__device__ int    g_nbrT[KK * NN];      // 14.2 MB transposed indices

// ---- packed f32x2 helpers (sm_103a) ----
__device__ __forceinline__ unsigned long long pack2(float v) {
    unsigned long long r;
    unsigned int u = __float_as_uint(v);
    asm("mov.b64 %0, {%1, %1};" : "=l"(r) : "r"(u));
    return r;
}
__device__ __forceinline__ void fma2(unsigned long long& d, unsigned long long a,
                                     unsigned long long b) {
    asm("fma.rn.f32x2 %0, %1, %2, %0;" : "+l"(d) : "l"(a), "l"(b));
}
__device__ __forceinline__ float2 unpack2(unsigned long long v) {
    unsigned int lo, hi;
    asm("mov.b64 {%0, %1}, %2;" : "=r"(lo), "=r"(hi) : "l"(v));
    return make_float2(__uint_as_float(lo), __uint_as_float(hi));
}

// ============================================================================
// k0: pack x [N,3] -> float4 table AND transpose nbr [N,27] -> nbrT [27,N]
// ============================================================================
__global__ __launch_bounds__(256) void k0(const float* __restrict__ x,
                                          const int* __restrict__ nbr) {
    __shared__ int s[256 * KK];          // 27.6 KB
    int tid = threadIdx.x;
    int base = blockIdx.x * 256;
    int n = base + tid;

    const float* r = x + (long)n * 3;
    g_x4[n] = make_float4(r[0], r[1], r[2], 0.0f);

    // coalesced row staging
    const int4* src = (const int4*)(nbr + (size_t)base * KK);
    int4* dst = (int4*)s;
    for (int i = tid; i < (256 * KK) / 4; i += 256) dst[i] = src[i];
    __syncthreads();
    // coalesced transposed writes (smem read stride 27 -> conflict-free)
#pragma unroll
    for (int k = 0; k < KK; k++)
        g_nbrT[(size_t)k * NN + n] = s[tid * KK + k];
}

// ============================================================================
// k1: h = SiLU(BN(einsum(x4[nbr], w1))) -> g_h
// ============================================================================
__global__ __launch_bounds__(256) void k1(const int* __restrict__ nbr,
                                          const float* __restrict__ w1,
                                          const float* __restrict__ gam,
                                          const float* __restrict__ bet,
                                          const float* __restrict__ mean,
                                          const float* __restrict__ var) {
    __shared__ float w1s[KK * FIN * FOUT];
    __shared__ int   idx_s[256 * KK];
    __shared__ float s_s[FOUT], s_t[FOUT];
    int tid = threadIdx.x;

    {
        const float4* wsrc = (const float4*)w1;
        float4* wdst = (float4*)w1s;
        for (int i = tid; i < (KK * FIN * FOUT) / 4; i += 256) wdst[i] = wsrc[i];
        const int4* isrc = (const int4*)(nbr + (size_t)blockIdx.x * 256 * KK);
        int4* idst = (int4*)idx_s;
        for (int i = tid; i < (256 * KK) / 4; i += 256) idst[i] = isrc[i];
        if (tid < FOUT) {
            float sc = gam[tid] * rsqrtf(var[tid] + EPSQ);
            s_s[tid] = sc;
            s_t[tid] = bet[tid] - mean[tid] * sc;
        }
    }
    __syncthreads();

    unsigned long long acc[16];
#pragma unroll
    for (int p = 0; p < 16; p++) acc[p] = 0ull;

#pragma unroll 1
    for (int k = 0; k < KK; k++) {
        int idx = idx_s[tid * KK + k];
        float4 xv = g_x4[idx];
        unsigned long long p0 = pack2(xv.x), p1 = pack2(xv.y), p2 = pack2(xv.z);
        const float* w = w1s + k * (FIN * FOUT);
        const ulonglong2* w0 = (const ulonglong2*)(w);
        const ulonglong2* w1p = (const ulonglong2*)(w + FOUT);
        const ulonglong2* w2p = (const ulonglong2*)(w + 2 * FOUT);
#pragma unroll
        for (int q = 0; q < 8; q++) {
            ulonglong2 a = w0[q];
            fma2(acc[2 * q], p0, a.x);
            fma2(acc[2 * q + 1], p0, a.y);
        }
#pragma unroll
        for (int q = 0; q < 8; q++) {
            ulonglong2 a = w1p[q];
            fma2(acc[2 * q], p1, a.x);
            fma2(acc[2 * q + 1], p1, a.y);
        }
#pragma unroll
        for (int q = 0; q < 8; q++) {
            ulonglong2 a = w2p[q];
            fma2(acc[2 * q], p2, a.x);
            fma2(acc[2 * q + 1], p2, a.y);
        }
    }

    int n = blockIdx.x * 256 + tid;
    float* hr = g_h + (long)n * FOUT;
#pragma unroll
    for (int q = 0; q < 8; q++) {
        float2 v0 = unpack2(acc[2 * q]);
        float2 v1 = unpack2(acc[2 * q + 1]);
        float r[4] = {v0.x, v0.y, v1.x, v1.y};
        float4 res;
        float* rp = &res.x;
#pragma unroll
        for (int j = 0; j < 4; j++) {
            int o = q * 4 + j;
            float v = r[j] * s_s[o] + s_t[o];
            rp[j] = v / (1.0f + __expf(-v));   // SiLU
        }
        ((float4*)hr)[q] = res;
    }
}

// ============================================================================
// k2: x_out = einsum(h[nbr], w2); out = x_out + relu(BN(z@mlp_w+b)) (x2 copies)
// 256 threads, 512 nodes/CTA. Thread = 4 nodes x 16 outputs.
// Per-k: stage w2[k] + coalesced-index gather of 512 h rows -> smem, compute.
// smem 78.5 KB -> 2 CTAs/SM.
// ============================================================================
#define SMEM2 ((NODES * HPAD + 1024 + 96 + 32 + 32) * 4 + 64)

extern "C" __global__ void __launch_bounds__(256, 2)
k2(const float* __restrict__ z_feats, const float* __restrict__ w2,
   const float* __restrict__ mlp_w, const float* __restrict__ mlp_b,
   const float* __restrict__ mg, const float* __restrict__ mbeta,
   const float* __restrict__ mm, const float* __restrict__ mv,
   float* __restrict__ out) {
    extern __shared__ float smem[];
    float* h_s    = smem;                  // 512*36
    float* w_s    = smem + NODES * HPAD;   // 1024
    float* mws    = w_s + 1024;            // 96
    float* mscale = mws + 96;              // 32
    float* mbias  = mscale + 32;           // 32

    int tid = threadIdx.x;
    int base = blockIdx.x * NODES;
    int og = tid & 1;        // output half (0/1)
    int ng = tid >> 1;       // node group (0..127) -> nodes ng*4..ng*4+3

    for (int i = tid; i < 96; i += 256) mws[i] = mlp_w[i];
    if (tid < FOUT) {
        float sc = mg[tid] * rsqrtf(mv[tid] + EPSQ);
        mscale[tid] = sc;
        mbias[tid] = (mlp_b[tid] - mm[tid]) * sc + mbeta[tid];
    }

    unsigned long long a[4][8];
#pragma unroll
    for (int i = 0; i < 4; i++)
#pragma unroll
        for (int q = 0; q < 8; q++) a[i][q] = 0ull;

#pragma unroll 1
    for (int k = 0; k < KK; k++) {
        __syncthreads();   // previous h_s/w_s readers done
        // stage w2[k] (coalesced, 1 float4/thread)
        ((float4*)w_s)[tid] = ((const float4*)(w2 + k * 1024))[tid];
        // gather 512 h rows; idx via coalesced/broadcast read of nbrT column
        const int* idxp = g_nbrT + (size_t)k * NN + base;
#pragma unroll
        for (int i = 0; i < 16; i++) {
            int c = tid + i * 256;
            int row = c >> 3, ch = c & 7;
            int idx = __ldg(idxp + row);
            float4 v = *(const float4*)(g_h + (size_t)idx * FOUT + ch * 4);
            *(float4*)(h_s + row * HPAD + ch * 4) = v;
        }
        __syncthreads();

        const float* hbase = h_s + ng * 4 * HPAD;
        const float* wbase = w_s + og * 16;
#pragma unroll
        for (int fc = 0; fc < 8; fc++) {
            float4 hv[4];
#pragma unroll
            for (int i = 0; i < 4; i++)
                hv[i] = *(const float4*)(hbase + i * HPAD + fc * 4);
#pragma unroll
            for (int j = 0; j < 4; j++) {
                int f = fc * 4 + j;
                const ulonglong2* wr = (const ulonglong2*)(wbase + f * FOUT);
                ulonglong2 wa = wr[0], wb = wr[1];
                unsigned long long p[4];
#pragma unroll
                for (int i = 0; i < 4; i++)
                    p[i] = pack2(((const float*)&hv[i])[j]);
#pragma unroll
                for (int i = 0; i < 4; i++) {
                    fma2(a[i][0], p[i], wa.x);
                    fma2(a[i][1], p[i], wa.y);
                    fma2(a[i][2], p[i], wb.x);
                    fma2(a[i][3], p[i], wb.y);
                }
                ulonglong2 wc = wr[2], wd = wr[3];
#pragma unroll
                for (int i = 0; i < 4; i++) {
                    fma2(a[i][4], p[i], wc.x);
                    fma2(a[i][5], p[i], wc.y);
                    fma2(a[i][6], p[i], wd.x);
                    fma2(a[i][7], p[i], wd.y);
                }
            }
        }
    }

    // epilogue: point branch + dual write (thread owns 4 nodes x 16 outs)
#pragma unroll
    for (int i = 0; i < 4; i++) {
        int n = base + ng * 4 + i;
        float zf0 = z_feats[(long)n * 3 + 0];
        float zf1 = z_feats[(long)n * 3 + 1];
        float zf2 = z_feats[(long)n * 3 + 2];
        float res[16];
#pragma unroll
        for (int q = 0; q < 8; q++) {
            float2 v = unpack2(a[i][q]);
            float rr[2] = {v.x, v.y};
#pragma unroll
            for (int u = 0; u < 2; u++) {
                int o = og * 16 + q * 2 + u;
                float zp = zf0 * mws[o] + zf1 * mws[32 + o] + zf2 * mws[64 + o];
                float z = zp * mscale[o] + mbias[o];
                res[q * 2 + u] = rr[u] + fmaxf(z, 0.0f);
            }
        }
        float* o0 = out + (size_t)n * FOUT + og * 16;
        float* o1 = o0 + (size_t)NN * FOUT;
#pragma unroll
        for (int q = 0; q < 4; q++) {
            float4 v = ((const float4*)res)[q];
            ((float4*)o0)[q] = v;
            ((float4*)o1)[q] = v;
        }
    }
}

// ============================================================================
extern "C" void kernel_launch(void* const* d_in, const int* in_sizes, int n_in,
                              void* d_out, int out_size) {
    const float* x_feats   = (const float*)d_in[0];
    const float* z_feats   = (const float*)d_in[1];
    const int*   nbr_idx   = (const int*)d_in[2];
    const float* w1        = (const float*)d_in[3];
    const float* bn1_gamma = (const float*)d_in[4];
    const float* bn1_beta  = (const float*)d_in[5];
    const float* bn1_mean  = (const float*)d_in[6];
    const float* bn1_var   = (const float*)d_in[7];
    const float* w2        = (const float*)d_in[8];
    const float* mlp_w     = (const float*)d_in[9];
    const float* mlp_b     = (const float*)d_in[10];
    const float* mlp_gamma = (const float*)d_in[11];
    const float* mlp_beta  = (const float*)d_in[12];
    const float* mlp_mean  = (const float*)d_in[13];
    const float* mlp_var   = (const float*)d_in[14];
    float* out = (float*)d_out;

    cudaFuncSetAttribute(k2, cudaFuncAttributeMaxDynamicSharedMemorySize, SMEM2);

    k0<<<NN / 256, 256>>>(x_feats, nbr_idx);
    k1<<<NN / 256, 256>>>(nbr_idx, w1, bn1_gamma, bn1_beta, bn1_mean, bn1_var);
    k2<<<NN / NODES, 256, SMEM2>>>(z_feats, w2, mlp_w, mlp_b, mlp_gamma,
                                   mlp_beta, mlp_mean, mlp_var, out);
}

// round 4
// speedup vs baseline: 1.0055x; 1.0055x over previous
#include <cuda_runtime.h>

#define NN   131072
#define KK   27
#define FIN  3
#define FOUT 32
#define EPSQ 1e-5f

#define NODES  512
#define HPAD   36

// allocation-free scratch
__device__ float  g_h[NN * FOUT];       // 16 MB intermediate h
__device__ float4 g_x4[NN];             // 2 MB padded x
__device__ int    g_nbrT[KK * NN];      // 14.2 MB transposed indices

// ---- packed f32x2 helpers (sm_103a) ----
__device__ __forceinline__ unsigned long long pack2(float v) {
    unsigned long long r;
    unsigned int u = __float_as_uint(v);
    asm("mov.b64 %0, {%1, %1};" : "=l"(r) : "r"(u));
    return r;
}
__device__ __forceinline__ void fma2(unsigned long long& d, unsigned long long a,
                                     unsigned long long b) {
    asm("fma.rn.f32x2 %0, %1, %2, %0;" : "+l"(d) : "l"(a), "l"(b));
}
__device__ __forceinline__ float2 unpack2(unsigned long long v) {
    unsigned int lo, hi;
    asm("mov.b64 {%0, %1}, %2;" : "=r"(lo), "=r"(hi) : "l"(v));
    return make_float2(__uint_as_float(lo), __uint_as_float(hi));
}

// ============================================================================
// k0: pack x [N,3] -> float4 table AND transpose nbr [N,27] -> nbrT [27,N]
// ============================================================================
__global__ __launch_bounds__(256) void k0(const float* __restrict__ x,
                                          const int* __restrict__ nbr) {
    __shared__ int s[256 * KK];          // 27.6 KB
    int tid = threadIdx.x;
    int base = blockIdx.x * 256;
    int n = base + tid;

    const float* r = x + (long)n * 3;
    g_x4[n] = make_float4(r[0], r[1], r[2], 0.0f);

    // coalesced row staging
    const int4* src = (const int4*)(nbr + (size_t)base * KK);
    int4* dst = (int4*)s;
    for (int i = tid; i < (256 * KK) / 4; i += 256) dst[i] = src[i];
    __syncthreads();
    // coalesced transposed writes (smem read stride 27 -> conflict-free)
#pragma unroll
    for (int k = 0; k < KK; k++)
        g_nbrT[(size_t)k * NN + n] = s[tid * KK + k];
}

// ============================================================================
// k1: h = SiLU(BN(einsum(x4[nbr], w1))) -> g_h
// ============================================================================
__global__ __launch_bounds__(256) void k1(const int* __restrict__ nbr,
                                          const float* __restrict__ w1,
                                          const float* __restrict__ gam,
                                          const float* __restrict__ bet,
                                          const float* __restrict__ mean,
                                          const float* __restrict__ var) {
    __shared__ float w1s[KK * FIN * FOUT];
    __shared__ int   idx_s[256 * KK];
    __shared__ float s_s[FOUT], s_t[FOUT];
    int tid = threadIdx.x;

    {
        const float4* wsrc = (const float4*)w1;
        float4* wdst = (float4*)w1s;
        for (int i = tid; i < (KK * FIN * FOUT) / 4; i += 256) wdst[i] = wsrc[i];
        const int4* isrc = (const int4*)(nbr + (size_t)blockIdx.x * 256 * KK);
        int4* idst = (int4*)idx_s;
        for (int i = tid; i < (256 * KK) / 4; i += 256) idst[i] = isrc[i];
        if (tid < FOUT) {
            float sc = gam[tid] * rsqrtf(var[tid] + EPSQ);
            s_s[tid] = sc;
            s_t[tid] = bet[tid] - mean[tid] * sc;
        }
    }
    __syncthreads();

    unsigned long long acc[16];
#pragma unroll
    for (int p = 0; p < 16; p++) acc[p] = 0ull;

#pragma unroll 1
    for (int k = 0; k < KK; k++) {
        int idx = idx_s[tid * KK + k];
        float4 xv = g_x4[idx];
        unsigned long long p0 = pack2(xv.x), p1 = pack2(xv.y), p2 = pack2(xv.z);
        const float* w = w1s + k * (FIN * FOUT);
        const ulonglong2* w0 = (const ulonglong2*)(w);
        const ulonglong2* w1p = (const ulonglong2*)(w + FOUT);
        const ulonglong2* w2p = (const ulonglong2*)(w + 2 * FOUT);
#pragma unroll
        for (int q = 0; q < 8; q++) {
            ulonglong2 a = w0[q];
            fma2(acc[2 * q], p0, a.x);
            fma2(acc[2 * q + 1], p0, a.y);
        }
#pragma unroll
        for (int q = 0; q < 8; q++) {
            ulonglong2 a = w1p[q];
            fma2(acc[2 * q], p1, a.x);
            fma2(acc[2 * q + 1], p1, a.y);
        }
#pragma unroll
        for (int q = 0; q < 8; q++) {
            ulonglong2 a = w2p[q];
            fma2(acc[2 * q], p2, a.x);
            fma2(acc[2 * q + 1], p2, a.y);
        }
    }

    int n = blockIdx.x * 256 + tid;
    float* hr = g_h + (long)n * FOUT;
#pragma unroll
    for (int q = 0; q < 8; q++) {
        float2 v0 = unpack2(acc[2 * q]);
        float2 v1 = unpack2(acc[2 * q + 1]);
        float r[4] = {v0.x, v0.y, v1.x, v1.y};
        float4 res;
        float* rp = &res.x;
#pragma unroll
        for (int j = 0; j < 4; j++) {
            int o = q * 4 + j;
            float v = r[j] * s_s[o] + s_t[o];
            rp[j] = v / (1.0f + __expf(-v));   // SiLU
        }
        ((float4*)hr)[q] = res;
    }
}

// ============================================================================
// k2: x_out = einsum(h[nbr], w2); out = x_out + relu(BN(z@mlp_w+b)) (x2 copies)
// 256 threads, 512 nodes/CTA. Thread = 4 nodes x 16 outputs.
// Per-k: stage w2[k] + coalesced-index gather of 512 h rows -> smem, compute.
// smem 78.5 KB -> 2 CTAs/SM.
// ============================================================================
#define SMEM2 ((NODES * HPAD + 1024 + 96 + 32 + 32) * 4 + 64)

extern "C" __global__ void __launch_bounds__(256, 2)
k2(const float* __restrict__ z_feats, const float* __restrict__ w2,
   const float* __restrict__ mlp_w, const float* __restrict__ mlp_b,
   const float* __restrict__ mg, const float* __restrict__ mbeta,
   const float* __restrict__ mm, const float* __restrict__ mv,
   float* __restrict__ out) {
    extern __shared__ float smem[];
    float* h_s    = smem;                  // 512*36
    float* w_s    = smem + NODES * HPAD;   // 1024
    float* mws    = w_s + 1024;            // 96
    float* mscale = mws + 96;              // 32
    float* mbias  = mscale + 32;           // 32

    int tid = threadIdx.x;
    int base = blockIdx.x * NODES;
    int og = tid & 1;        // output half (0/1)
    int ng = tid >> 1;       // node group (0..127) -> nodes ng*4..ng*4+3

    for (int i = tid; i < 96; i += 256) mws[i] = mlp_w[i];
    if (tid < FOUT) {
        float sc = mg[tid] * rsqrtf(mv[tid] + EPSQ);
        mscale[tid] = sc;
        mbias[tid] = (mlp_b[tid] - mm[tid]) * sc + mbeta[tid];
    }

    unsigned long long a[4][8];
#pragma unroll
    for (int i = 0; i < 4; i++)
#pragma unroll
        for (int q = 0; q < 8; q++) a[i][q] = 0ull;

#pragma unroll 1
    for (int k = 0; k < KK; k++) {
        __syncthreads();   // previous h_s/w_s readers done
        // stage w2[k] (coalesced, 1 float4/thread)
        ((float4*)w_s)[tid] = ((const float4*)(w2 + k * 1024))[tid];
        // gather 512 h rows; idx via coalesced/broadcast read of nbrT column
        const int* idxp = g_nbrT + (size_t)k * NN + base;
#pragma unroll
        for (int i = 0; i < 16; i++) {
            int c = tid + i * 256;
            int row = c >> 3, ch = c & 7;
            int idx = __ldg(idxp + row);
            float4 v = *(const float4*)(g_h + (size_t)idx * FOUT + ch * 4);
            *(float4*)(h_s + row * HPAD + ch * 4) = v;
        }
        __syncthreads();

        const float* hbase = h_s + ng * 4 * HPAD;
        const float* wbase = w_s + og * 16;
#pragma unroll
        for (int fc = 0; fc < 8; fc++) {
            float4 hv[4];
#pragma unroll
            for (int i = 0; i < 4; i++)
                hv[i] = *(const float4*)(hbase + i * HPAD + fc * 4);
#pragma unroll
            for (int j = 0; j < 4; j++) {
                int f = fc * 4 + j;
                const ulonglong2* wr = (const ulonglong2*)(wbase + f * FOUT);
                ulonglong2 wa = wr[0], wb = wr[1];
                unsigned long long p[4];
#pragma unroll
                for (int i = 0; i < 4; i++)
                    p[i] = pack2(((const float*)&hv[i])[j]);
#pragma unroll
                for (int i = 0; i < 4; i++) {
                    fma2(a[i][0], p[i], wa.x);
                    fma2(a[i][1], p[i], wa.y);
                    fma2(a[i][2], p[i], wb.x);
                    fma2(a[i][3], p[i], wb.y);
                }
                ulonglong2 wc = wr[2], wd = wr[3];
#pragma unroll
                for (int i = 0; i < 4; i++) {
                    fma2(a[i][4], p[i], wc.x);
                    fma2(a[i][5], p[i], wc.y);
                    fma2(a[i][6], p[i], wd.x);
                    fma2(a[i][7], p[i], wd.y);
                }
            }
        }
    }

    // epilogue: point branch + dual write (thread owns 4 nodes x 16 outs)
#pragma unroll
    for (int i = 0; i < 4; i++) {
        int n = base + ng * 4 + i;
        float zf0 = z_feats[(long)n * 3 + 0];
        float zf1 = z_feats[(long)n * 3 + 1];
        float zf2 = z_feats[(long)n * 3 + 2];
        float res[16];
#pragma unroll
        for (int q = 0; q < 8; q++) {
            float2 v = unpack2(a[i][q]);
            float rr[2] = {v.x, v.y};
#pragma unroll
            for (int u = 0; u < 2; u++) {
                int o = og * 16 + q * 2 + u;
                float zp = zf0 * mws[o] + zf1 * mws[32 + o] + zf2 * mws[64 + o];
                float z = zp * mscale[o] + mbias[o];
                res[q * 2 + u] = rr[u] + fmaxf(z, 0.0f);
            }
        }
        float* o0 = out + (size_t)n * FOUT + og * 16;
        float* o1 = o0 + (size_t)NN * FOUT;
#pragma unroll
        for (int q = 0; q < 4; q++) {
            float4 v = ((const float4*)res)[q];
            ((float4*)o0)[q] = v;
            ((float4*)o1)[q] = v;
        }
    }
}

// ============================================================================
extern "C" void kernel_launch(void* const* d_in, const int* in_sizes, int n_in,
                              void* d_out, int out_size) {
    const float* x_feats   = (const float*)d_in[0];
    const float* z_feats   = (const float*)d_in[1];
    const int*   nbr_idx   = (const int*)d_in[2];
    const float* w1        = (const float*)d_in[3];
    const float* bn1_gamma = (const float*)d_in[4];
    const float* bn1_beta  = (const float*)d_in[5];
    const float* bn1_mean  = (const float*)d_in[6];
    const float* bn1_var   = (const float*)d_in[7];
    const float* w2        = (const float*)d_in[8];
    const float* mlp_w     = (const float*)d_in[9];
    const float* mlp_b     = (const float*)d_in[10];
    const float* mlp_gamma = (const float*)d_in[11];
    const float* mlp_beta  = (const float*)d_in[12];
    const float* mlp_mean  = (const float*)d_in[13];
    const float* mlp_var   = (const float*)d_in[14];
    float* out = (float*)d_out;

    cudaFuncSetAttribute(k2, cudaFuncAttributeMaxDynamicSharedMemorySize, SMEM2);

    k0<<<NN / 256, 256>>>(x_feats, nbr_idx);
    k1<<<NN / 256, 256>>>(nbr_idx, w1, bn1_gamma, bn1_beta, bn1_mean, bn1_var);
    k2<<<NN / NODES, 256, SMEM2>>>(z_feats, w2, mlp_w, mlp_b, mlp_gamma,
                                   mlp_beta, mlp_mean, mlp_var, out);
}